// round 6
// baseline (speedup 1.0000x reference)
#include <cuda_runtime.h>
#include <cuda_fp16.h>
#include <cstdint>

// ---------------------------------------------------------------------------
// Problem constants
// ---------------------------------------------------------------------------
#define B_TOK  65536
#define IN_D   1280
#define NEXP   8
#define HID1   256
#define HID2   128
#define N_TOT  2048              // NEXP * HID1
#define KC     64                // K chunk (64 halfs = 128B rows)

// ---------------------------------------------------------------------------
// Scratch (device globals: allocation-free rule)
// ---------------------------------------------------------------------------
__device__ __half g_xh [(size_t)B_TOK * IN_D];       // x in fp16        (160 MB)
__device__ __half g_w1t[(size_t)N_TOT * IN_D];       // W1 packed [n][k] (5.2 MB)
__device__ __half g_h1 [(size_t)B_TOK * N_TOT];      // h1 fp16          (256 MB)
__device__ __half g_w2t[(size_t)NEXP * HID2 * HID1]; // W2 packed [e][n][k]

// ---------------------------------------------------------------------------
// PTX helpers (base sm_103 — NO tcgen05; mma.sync + ldmatrix + cp.async only)
// ---------------------------------------------------------------------------
__device__ __forceinline__ uint32_t su32(const void* p) {
    uint32_t a;
    asm("{ .reg .u64 t; cvta.to.shared.u64 t, %1; cvt.u32.u64 %0, t; }"
        : "=r"(a) : "l"(p));
    return a;
}

__device__ __forceinline__ void cpasync16(uint32_t dst, const void* src) {
    asm volatile("cp.async.cg.shared.global [%0], [%1], 16;"
                 :: "r"(dst), "l"(src) : "memory");
}
#define CP_COMMIT() asm volatile("cp.async.commit_group;" ::: "memory")
#define CP_WAIT(n)  asm volatile("cp.async.wait_group %0;" :: "n"(n) : "memory")

__device__ __forceinline__ void ldsm4(uint32_t (&r)[4], uint32_t addr) {
    asm volatile("ldmatrix.sync.aligned.m8n8.x4.shared.b16 {%0,%1,%2,%3}, [%4];"
                 : "=r"(r[0]), "=r"(r[1]), "=r"(r[2]), "=r"(r[3]) : "r"(addr));
}

__device__ __forceinline__ void mma16816(float* d, const uint32_t* a,
                                         uint32_t b0, uint32_t b1) {
    asm volatile(
        "mma.sync.aligned.m16n8k16.row.col.f32.f16.f16.f32 "
        "{%0,%1,%2,%3},{%4,%5,%6,%7},{%8,%9},{%0,%1,%2,%3};"
        : "+f"(d[0]), "+f"(d[1]), "+f"(d[2]), "+f"(d[3])
        : "r"(a[0]), "r"(a[1]), "r"(a[2]), "r"(a[3]), "r"(b0), "r"(b1));
}

#define SW128(o) ((o) ^ (((o) >> 3) & 0x70))

__device__ __forceinline__ uint32_t packh(float a, float b) {
    __half2 h = __floats2half2_rn(a, b);
    return *reinterpret_cast<uint32_t*>(&h);
}

// ---------------------------------------------------------------------------
// Kernel 1: pack weights into fp16 K-major B-operand layouts
// ---------------------------------------------------------------------------
__global__ void pack_weights_kernel(const float* __restrict__ W1,
                                    const float* __restrict__ W2) {
    const int stride = gridDim.x * blockDim.x;
    int idx = blockIdx.x * blockDim.x + threadIdx.x;
    // g_w1t[n][k] = W1[e=n/256][k][h=n%256]
    for (int i = idx; i < N_TOT * IN_D; i += stride) {
        int n = i / IN_D, k = i % IN_D;
        g_w1t[i] = __float2half_rn(W1[((size_t)(n >> 8) * IN_D + k) * HID1 + (n & 255)]);
    }
    // g_w2t[e][n=h2][k=h1] = W2[e][k][n]
    for (int i = idx; i < NEXP * HID2 * HID1; i += stride) {
        int e = i >> 15;
        int r = i & 32767;
        int n = r >> 8;           // h2  (0..127)
        int k = r & 255;          // h1  (0..255)
        g_w2t[i] = __float2half_rn(W2[(size_t)e * HID1 * HID2 + (size_t)k * HID2 + n]);
    }
}

// ---------------------------------------------------------------------------
// Kernel 2: gate (fp32, one warp per token) + x -> fp16 conversion
// ---------------------------------------------------------------------------
__global__ __launch_bounds__(256) void gate_convert_kernel(
    const float* __restrict__ x, const float* __restrict__ Wg,
    const float* __restrict__ bg, float* __restrict__ out) {
    const int warp = (blockIdx.x * blockDim.x + threadIdx.x) >> 5;  // token id
    const int lane = threadIdx.x & 31;
    const float* xr = x + (size_t)warp * IN_D;
    __half* xo = g_xh + (size_t)warp * IN_D;

    float acc[NEXP];
#pragma unroll
    for (int e = 0; e < NEXP; ++e) acc[e] = 0.f;

    for (int k = lane; k < IN_D; k += 32) {
        float xv = xr[k];
        xo[k] = __float2half_rn(xv);
        float4 wa = *reinterpret_cast<const float4*>(Wg + (size_t)k * NEXP);
        float4 wb = *reinterpret_cast<const float4*>(Wg + (size_t)k * NEXP + 4);
        acc[0] += xv * wa.x; acc[1] += xv * wa.y;
        acc[2] += xv * wa.z; acc[3] += xv * wa.w;
        acc[4] += xv * wb.x; acc[5] += xv * wb.y;
        acc[6] += xv * wb.z; acc[7] += xv * wb.w;
    }
#pragma unroll
    for (int e = 0; e < NEXP; ++e) {
        float v = acc[e];
        v += __shfl_xor_sync(0xFFFFFFFFu, v, 16);
        v += __shfl_xor_sync(0xFFFFFFFFu, v, 8);
        v += __shfl_xor_sync(0xFFFFFFFFu, v, 4);
        v += __shfl_xor_sync(0xFFFFFFFFu, v, 2);
        v += __shfl_xor_sync(0xFFFFFFFFu, v, 1);
        acc[e] = v + bg[e];
    }
    float m = acc[0];
#pragma unroll
    for (int e = 1; e < NEXP; ++e) m = fmaxf(m, acc[e]);
    float s = 0.f;
#pragma unroll
    for (int e = 0; e < NEXP; ++e) { acc[e] = expf(acc[e] - m); s += acc[e]; }
    float inv = 1.f / s;
    if (lane < NEXP)
        out[(size_t)B_TOK + (size_t)warp * NEXP + lane] = acc[lane] * inv;
}

// ---------------------------------------------------------------------------
// Kernel 3: GEMM1 h1 = relu(x @ W1cat + b1)
//   CTA tile 128(M) x 256(N), 256 thr = 8 warps (2x4), warp tile 64x64
//   K pipeline: chunks of 64, 3 cp.async stages
//   smem per stage: A 16KB + B 32KB = 48KB -> 144KB total
// ---------------------------------------------------------------------------
#define G1_STAGE 49152
__global__ __launch_bounds__(256, 1)
void gemm1_kernel(const float* __restrict__ b1) {
    extern __shared__ char smem[];
    const uint32_t sb = su32(smem);
    const int tid = threadIdx.x, lane = tid & 31, wid = tid >> 5;
    const int m0 = blockIdx.y * 128;
    const int n0 = blockIdx.x * 256;
    const int wm = wid >> 2, wn = wid & 3;   // warp grid 2 x 4

    const __half* Abase = g_xh  + (size_t)m0 * IN_D;
    const __half* Bbase = g_w1t + (size_t)n0 * IN_D;

    float acc[4][8][4];
#pragma unroll
    for (int i = 0; i < 4; ++i)
#pragma unroll
        for (int j = 0; j < 8; ++j)
#pragma unroll
            for (int q = 0; q < 4; ++q) acc[i][j][q] = 0.f;

    // ---- async loader ----
    auto load_stage = [&](int it, int s) {
        const int k0 = it * KC;
        const uint32_t sA = sb + s * G1_STAGE;
        const uint32_t sB = sA + 16384;
#pragma unroll
        for (int i = 0; i < 4; ++i) {                 // A: 1024 16B chunks
            int id = tid + i * 256;
            int r = id >> 3, c = id & 7;
            cpasync16(sA + SW128(r * 128 + c * 16),
                      Abase + (size_t)r * IN_D + k0 + c * 8);
        }
#pragma unroll
        for (int i = 0; i < 8; ++i) {                 // B: 2048 16B chunks
            int id = tid + i * 256;
            int r = id >> 3, c = id & 7;
            cpasync16(sB + SW128(r * 128 + c * 16),
                      Bbase + (size_t)r * IN_D + k0 + c * 8);
        }
        CP_COMMIT();
    };

    const int NIT = IN_D / KC;   // 20
    load_stage(0, 0);
    load_stage(1, 1);

    const int lrow = lane & 15;
    const int lcol = (lane >> 4) * 16;    // byte offset of k-half

    for (int it = 0; it < NIT; ++it) {
        if (it == NIT - 1) { CP_WAIT(0); } else { CP_WAIT(1); }
        __syncthreads();
        if (it + 2 < NIT) load_stage(it + 2, (it + 2) % 3);

        const uint32_t sA = sb + (it % 3) * G1_STAGE;
        const uint32_t sB = sA + 16384;
#pragma unroll
        for (int k16 = 0; k16 < 4; ++k16) {
            const int kb = k16 * 32 + lcol;
            uint32_t af[4][4];
#pragma unroll
            for (int mf = 0; mf < 4; ++mf) {
                int r = wm * 64 + mf * 16 + lrow;
                ldsm4(af[mf], sA + SW128(r * 128 + kb));
            }
            uint32_t bf[4][4];
#pragma unroll
            for (int nf2 = 0; nf2 < 4; ++nf2) {
                int r = wn * 64 + nf2 * 16 + lrow;
                ldsm4(bf[nf2], sB + SW128(r * 128 + kb));
            }
#pragma unroll
            for (int mf = 0; mf < 4; ++mf)
#pragma unroll
                for (int nf = 0; nf < 8; ++nf)
                    mma16816(acc[mf][nf], af[mf],
                             bf[nf >> 1][nf & 1], bf[nf >> 1][2 + (nf & 1)]);
        }
        __syncthreads();
    }

    // ---- epilogue: bias + relu -> fp16 -> g_h1 ----
    float2 bias[8];
#pragma unroll
    for (int nf = 0; nf < 8; ++nf) {
        int n = n0 + wn * 64 + nf * 8 + (lane & 3) * 2;
        bias[nf] = make_float2(b1[n], b1[n + 1]);
    }
#pragma unroll
    for (int mf = 0; mf < 4; ++mf) {
        int mA = m0 + wm * 64 + mf * 16 + (lane >> 2);
        __half* row0 = g_h1 + (size_t)mA * N_TOT;
        __half* row1 = row0 + (size_t)8 * N_TOT;
#pragma unroll
        for (int nf = 0; nf < 8; ++nf) {
            int n = n0 + wn * 64 + nf * 8 + (lane & 3) * 2;
            float v0 = fmaxf(acc[mf][nf][0] + bias[nf].x, 0.f);
            float v1 = fmaxf(acc[mf][nf][1] + bias[nf].y, 0.f);
            float v2 = fmaxf(acc[mf][nf][2] + bias[nf].x, 0.f);
            float v3 = fmaxf(acc[mf][nf][3] + bias[nf].y, 0.f);
            *reinterpret_cast<uint32_t*>(row0 + n) = packh(v0, v1);
            *reinterpret_cast<uint32_t*>(row1 + n) = packh(v2, v3);
        }
    }
}

// ---------------------------------------------------------------------------
// Kernel 4: GEMM2 + layer3 + gate-weighted sum -> predictions
//   CTA 128(M) x 128(N=H2), 256 thr, warp tile 64x32 (2x4 grid)
//   32 pipelined chunks = 8 experts x 4 k-chunks; smem 3 x 32KB + partials
// ---------------------------------------------------------------------------
#define G2_STAGE 32768
__global__ __launch_bounds__(256, 1)
void gemm2_kernel(const float* __restrict__ b2, const float* __restrict__ W3,
                  const float* __restrict__ b3, float* __restrict__ out) {
    extern __shared__ char smem[];
    const uint32_t sb = su32(smem);
    float* s_part = reinterpret_cast<float*>(smem + 3 * G2_STAGE); // [128][4]
    const int tid = threadIdx.x, lane = tid & 31, wid = tid >> 5;
    const int m0 = blockIdx.x * 128;
    const int wm = wid >> 2, wn = wid & 3;

    float predv = 0.f;

    auto load_stage = [&](int c, int s) {
        const int e = c >> 2, kb = (c & 3) * KC;
        const __half* Ab = g_h1  + (size_t)m0 * N_TOT + e * HID1 + kb;
        const __half* Bb = g_w2t + (size_t)e * HID2 * HID1 + kb;
        const uint32_t sA = sb + s * G2_STAGE;
        const uint32_t sB = sA + 16384;
#pragma unroll
        for (int i = 0; i < 4; ++i) {                 // A: 128 x 128B
            int id = tid + i * 256;
            int r = id >> 3, cc = id & 7;
            cpasync16(sA + SW128(r * 128 + cc * 16),
                      Ab + (size_t)r * N_TOT + cc * 8);
        }
#pragma unroll
        for (int i = 0; i < 4; ++i) {                 // B: 128 x 128B
            int id = tid + i * 256;
            int r = id >> 3, cc = id & 7;
            cpasync16(sB + SW128(r * 128 + cc * 16),
                      Bb + (size_t)r * HID1 + cc * 8);
        }
        CP_COMMIT();
    };

    load_stage(0, 0);
    load_stage(1, 1);

    const int lrow = lane & 15;
    const int lcol = (lane >> 4) * 16;

    float acc[4][4][4];

    for (int c = 0; c < 32; ++c) {
        const int e = c >> 2, kb = c & 3;
        if (kb == 0) {
#pragma unroll
            for (int i = 0; i < 4; ++i)
#pragma unroll
                for (int j = 0; j < 4; ++j)
#pragma unroll
                    for (int q = 0; q < 4; ++q) acc[i][j][q] = 0.f;
        }

        if (c == 31) { CP_WAIT(0); } else { CP_WAIT(1); }
        __syncthreads();
        if (c + 2 < 32) load_stage(c + 2, (c + 2) % 3);

        const uint32_t sA = sb + (c % 3) * G2_STAGE;
        const uint32_t sB = sA + 16384;
#pragma unroll
        for (int k16 = 0; k16 < 4; ++k16) {
            const int kbyte = k16 * 32 + lcol;
            uint32_t af[4][4];
#pragma unroll
            for (int mf = 0; mf < 4; ++mf) {
                int r = wm * 64 + mf * 16 + lrow;
                ldsm4(af[mf], sA + SW128(r * 128 + kbyte));
            }
            uint32_t bf[2][4];
#pragma unroll
            for (int nf2 = 0; nf2 < 2; ++nf2) {
                int r = wn * 32 + nf2 * 16 + lrow;
                ldsm4(bf[nf2], sB + SW128(r * 128 + kbyte));
            }
#pragma unroll
            for (int mf = 0; mf < 4; ++mf)
#pragma unroll
                for (int nf = 0; nf < 4; ++nf)
                    mma16816(acc[mf][nf], af[mf],
                             bf[nf >> 1][nf & 1], bf[nf >> 1][2 + (nf & 1)]);
        }
        __syncthreads();

        if (kb == 3) {
            // relu(h2 + b2) . W3 per row, gate-weighted accumulate
#pragma unroll
            for (int mf = 0; mf < 4; ++mf) {
#pragma unroll
                for (int h = 0; h < 2; ++h) {
                    float s = 0.f;
#pragma unroll
                    for (int nf = 0; nf < 4; ++nf) {
                        int n = wn * 32 + nf * 8 + (lane & 3) * 2;
                        float hv0 = fmaxf(acc[mf][nf][h * 2 + 0] + b2[e * HID2 + n], 0.f);
                        float hv1 = fmaxf(acc[mf][nf][h * 2 + 1] + b2[e * HID2 + n + 1], 0.f);
                        s += hv0 * W3[e * HID2 + n] + hv1 * W3[e * HID2 + n + 1];
                    }
                    s += __shfl_xor_sync(0xFFFFFFFFu, s, 1);
                    s += __shfl_xor_sync(0xFFFFFFFFu, s, 2);
                    if ((lane & 3) == 0) {
                        int m_local = wm * 64 + mf * 16 + h * 8 + (lane >> 2);
                        s_part[m_local * 4 + wn] = s;
                    }
                }
            }
            __syncthreads();
            if (tid < 128) {
                float dot = s_part[tid * 4 + 0] + s_part[tid * 4 + 1] +
                            s_part[tid * 4 + 2] + s_part[tid * 4 + 3];
                float g = out[(size_t)B_TOK + (size_t)(m0 + tid) * NEXP + e];
                predv += g * (dot + b3[e]);
            }
            __syncthreads();
        }
    }
    if (tid < 128) out[m0 + tid] = predv;
}

// ---------------------------------------------------------------------------
// Launch
// ---------------------------------------------------------------------------
extern "C" void kernel_launch(void* const* d_in, const int* in_sizes, int n_in,
                              void* d_out, int out_size) {
    const float* x  = (const float*)d_in[0];
    const float* W1 = (const float*)d_in[1];
    const float* b1 = (const float*)d_in[2];
    const float* W2 = (const float*)d_in[3];
    const float* b2 = (const float*)d_in[4];
    const float* W3 = (const float*)d_in[5];
    const float* b3 = (const float*)d_in[6];
    const float* Wg = (const float*)d_in[7];
    const float* bg = (const float*)d_in[8];
    float* out = (float*)d_out;

    const int SMEM1 = 3 * G1_STAGE;           // 147456
    const int SMEM2 = 3 * G2_STAGE + 2048;    // 100352
    cudaFuncSetAttribute(gemm1_kernel, cudaFuncAttributeMaxDynamicSharedMemorySize, SMEM1);
    cudaFuncSetAttribute(gemm2_kernel, cudaFuncAttributeMaxDynamicSharedMemorySize, SMEM2);

    pack_weights_kernel<<<512, 256>>>(W1, W2);
    gate_convert_kernel<<<B_TOK / 8, 256>>>(x, Wg, bg, out);
    gemm1_kernel<<<dim3(N_TOT / 256, B_TOK / 128), 256, SMEM1>>>(b1);
    gemm2_kernel<<<B_TOK / 128, 256, SMEM2>>>(b2, W3, b3, out);
}

// round 7
// speedup vs baseline: 1.0170x; 1.0170x over previous
#include <cuda_runtime.h>
#include <cuda_fp16.h>
#include <cstdint>

// ---------------------------------------------------------------------------
// Problem constants
// ---------------------------------------------------------------------------
#define B_TOK  65536
#define IN_D   1280
#define NEXP   8
#define HID1   256
#define HID2   128
#define N_TOT  2048              // NEXP * HID1
#define KC     64                // K chunk (64 halfs = 128B rows)

// ---------------------------------------------------------------------------
// Scratch (device globals: allocation-free rule)
// ---------------------------------------------------------------------------
__device__ __half g_xh [(size_t)B_TOK * IN_D];       // x in fp16        (160 MB)
__device__ __half g_w1t[(size_t)N_TOT * IN_D];       // W1 packed [n][k] (5.2 MB)
__device__ __half g_h1 [(size_t)B_TOK * N_TOT];      // h1 fp16          (256 MB)
__device__ __half g_w2t[(size_t)NEXP * HID2 * HID1]; // W2 packed [e][n][k]

// ---------------------------------------------------------------------------
// PTX helpers (base sm_103: mma.sync + ldmatrix + cp.async)
// ---------------------------------------------------------------------------
__device__ __forceinline__ uint32_t su32(const void* p) {
    uint32_t a;
    asm("{ .reg .u64 t; cvta.to.shared.u64 t, %1; cvt.u32.u64 %0, t; }"
        : "=r"(a) : "l"(p));
    return a;
}

__device__ __forceinline__ void cpasync16(uint32_t dst, const void* src) {
    asm volatile("cp.async.cg.shared.global [%0], [%1], 16;"
                 :: "r"(dst), "l"(src) : "memory");
}
#define CP_COMMIT() asm volatile("cp.async.commit_group;" ::: "memory")
#define CP_WAIT(n)  asm volatile("cp.async.wait_group %0;" :: "n"(n) : "memory")

__device__ __forceinline__ void ldsm4(uint32_t (&r)[4], uint32_t addr) {
    asm volatile("ldmatrix.sync.aligned.m8n8.x4.shared.b16 {%0,%1,%2,%3}, [%4];"
                 : "=r"(r[0]), "=r"(r[1]), "=r"(r[2]), "=r"(r[3]) : "r"(addr));
}

__device__ __forceinline__ void mma16816(float* d, const uint32_t* a,
                                         uint32_t b0, uint32_t b1) {
    asm volatile(
        "mma.sync.aligned.m16n8k16.row.col.f32.f16.f16.f32 "
        "{%0,%1,%2,%3},{%4,%5,%6,%7},{%8,%9},{%0,%1,%2,%3};"
        : "+f"(d[0]), "+f"(d[1]), "+f"(d[2]), "+f"(d[3])
        : "r"(a[0]), "r"(a[1]), "r"(a[2]), "r"(a[3]), "r"(b0), "r"(b1));
}

#define SW128(o) ((o) ^ (((o) >> 3) & 0x70))

__device__ __forceinline__ uint32_t packh(float a, float b) {
    __half2 h = __floats2half2_rn(a, b);
    return *reinterpret_cast<uint32_t*>(&h);
}

// ---------------------------------------------------------------------------
// Kernel 1: pack weights into fp16 K-major B-operand layouts
// ---------------------------------------------------------------------------
__global__ void pack_weights_kernel(const float* __restrict__ W1,
                                    const float* __restrict__ W2) {
    const int stride = gridDim.x * blockDim.x;
    int idx = blockIdx.x * blockDim.x + threadIdx.x;
    // g_w1t[n][k] = W1[e=n/256][k][h=n%256]
    for (int i = idx; i < N_TOT * IN_D; i += stride) {
        int n = i / IN_D, k = i % IN_D;
        g_w1t[i] = __float2half_rn(W1[((size_t)(n >> 8) * IN_D + k) * HID1 + (n & 255)]);
    }
    // g_w2t[e][n=h2][k=h1] = W2[e][k][n]
    for (int i = idx; i < NEXP * HID2 * HID1; i += stride) {
        int e = i >> 15;
        int r = i & 32767;
        int n = r >> 8;           // h2  (0..127)
        int k = r & 255;          // h1  (0..255)
        g_w2t[i] = __float2half_rn(W2[(size_t)e * HID1 * HID2 + (size_t)k * HID2 + n]);
    }
}

// ---------------------------------------------------------------------------
// Kernel 2: gate (fp32, one warp per token) + x -> fp16 conversion
// ---------------------------------------------------------------------------
__global__ __launch_bounds__(256) void gate_convert_kernel(
    const float* __restrict__ x, const float* __restrict__ Wg,
    const float* __restrict__ bg, float* __restrict__ out) {
    const int warp = (blockIdx.x * blockDim.x + threadIdx.x) >> 5;  // token id
    const int lane = threadIdx.x & 31;
    const float* xr = x + (size_t)warp * IN_D;
    __half* xo = g_xh + (size_t)warp * IN_D;

    float acc[NEXP];
#pragma unroll
    for (int e = 0; e < NEXP; ++e) acc[e] = 0.f;

    for (int k = lane; k < IN_D; k += 32) {
        float xv = xr[k];
        xo[k] = __float2half_rn(xv);
        float4 wa = *reinterpret_cast<const float4*>(Wg + (size_t)k * NEXP);
        float4 wb = *reinterpret_cast<const float4*>(Wg + (size_t)k * NEXP + 4);
        acc[0] += xv * wa.x; acc[1] += xv * wa.y;
        acc[2] += xv * wa.z; acc[3] += xv * wa.w;
        acc[4] += xv * wb.x; acc[5] += xv * wb.y;
        acc[6] += xv * wb.z; acc[7] += xv * wb.w;
    }
#pragma unroll
    for (int e = 0; e < NEXP; ++e) {
        float v = acc[e];
        v += __shfl_xor_sync(0xFFFFFFFFu, v, 16);
        v += __shfl_xor_sync(0xFFFFFFFFu, v, 8);
        v += __shfl_xor_sync(0xFFFFFFFFu, v, 4);
        v += __shfl_xor_sync(0xFFFFFFFFu, v, 2);
        v += __shfl_xor_sync(0xFFFFFFFFu, v, 1);
        acc[e] = v + bg[e];
    }
    float m = acc[0];
#pragma unroll
    for (int e = 1; e < NEXP; ++e) m = fmaxf(m, acc[e]);
    float s = 0.f;
#pragma unroll
    for (int e = 0; e < NEXP; ++e) { acc[e] = expf(acc[e] - m); s += acc[e]; }
    float inv = 1.f / s;
    if (lane < NEXP)
        out[(size_t)B_TOK + (size_t)warp * NEXP + lane] = acc[lane] * inv;
}

// ---------------------------------------------------------------------------
// Kernel 3: GEMM1 h1 = relu(x @ W1cat + b1)
//   CTA tile 128(M) x 256(N), 512 thr = 16 warps (2x8), warp tile 64x32
//   4-stage cp.async ring, ONE __syncthreads per K-chunk
//   stage: A 16KB + B 32KB = 48KB -> 192KB
// ---------------------------------------------------------------------------
#define G1_STAGE 49152
__global__ __launch_bounds__(512, 1)
void gemm1_kernel(const float* __restrict__ b1) {
    extern __shared__ char smem[];
    const uint32_t sb = su32(smem);
    const int tid = threadIdx.x, lane = tid & 31, wid = tid >> 5;
    const int m0 = blockIdx.y * 128;
    const int n0 = blockIdx.x * 256;
    const int wm = wid >> 3, wn = wid & 7;   // warp grid 2 x 8

    const __half* Abase = g_xh  + (size_t)m0 * IN_D;
    const __half* Bbase = g_w1t + (size_t)n0 * IN_D;

    float acc[4][4][4];
#pragma unroll
    for (int i = 0; i < 4; ++i)
#pragma unroll
        for (int j = 0; j < 4; ++j)
#pragma unroll
            for (int q = 0; q < 4; ++q) acc[i][j][q] = 0.f;

    const int NIT = IN_D / KC;   // 20

    // ---- async loader: stage s <- chunk it ----
#define G1_LOAD(it_, s_) do {                                                  \
        const int k0_ = (it_) * KC;                                            \
        const uint32_t sA_ = sb + (s_) * G1_STAGE;                             \
        const uint32_t sB_ = sA_ + 16384;                                      \
        _Pragma("unroll")                                                      \
        for (int i_ = 0; i_ < 2; ++i_) {        /* A: 1024 chunks */           \
            int id_ = tid + i_ * 512;                                          \
            int r_ = id_ >> 3, c_ = id_ & 7;                                   \
            cpasync16(sA_ + SW128(r_ * 128 + c_ * 16),                         \
                      Abase + (size_t)r_ * IN_D + k0_ + c_ * 8);               \
        }                                                                      \
        _Pragma("unroll")                                                      \
        for (int i_ = 0; i_ < 4; ++i_) {        /* B: 2048 chunks */           \
            int id_ = tid + i_ * 512;                                          \
            int r_ = id_ >> 3, c_ = id_ & 7;                                   \
            cpasync16(sB_ + SW128(r_ * 128 + c_ * 16),                         \
                      Bbase + (size_t)r_ * IN_D + k0_ + c_ * 8);               \
        }                                                                      \
        CP_COMMIT();                                                           \
    } while (0)

    G1_LOAD(0, 0);
    G1_LOAD(1, 1);
    G1_LOAD(2, 2);

    const int lrow = lane & 15;
    const int lcol = (lane >> 4) * 16;    // byte offset of k-half

    for (int it = 0; it < NIT; ++it) {
        CP_WAIT(2);            // stage (it) resident
        __syncthreads();       // all warps done with stage (it-1) -> safe reuse
        if (it + 3 < NIT) { G1_LOAD(it + 3, (it + 3) & 3); } else { CP_COMMIT(); }

        const uint32_t sA = sb + (it & 3) * G1_STAGE;
        const uint32_t sB = sA + 16384;
#pragma unroll
        for (int k16 = 0; k16 < 4; ++k16) {
            const int kb = k16 * 32 + lcol;
            uint32_t af[4][4];
#pragma unroll
            for (int mf = 0; mf < 4; ++mf)
                ldsm4(af[mf], sA + SW128((wm * 64 + mf * 16 + lrow) * 128 + kb));
            uint32_t bf[2][4];
#pragma unroll
            for (int nf2 = 0; nf2 < 2; ++nf2)
                ldsm4(bf[nf2], sB + SW128((wn * 32 + nf2 * 16 + lrow) * 128 + kb));
#pragma unroll
            for (int mf = 0; mf < 4; ++mf)
#pragma unroll
                for (int nf = 0; nf < 4; ++nf)
                    mma16816(acc[mf][nf], af[mf],
                             bf[nf >> 1][nf & 1], bf[nf >> 1][2 + (nf & 1)]);
        }
    }
#undef G1_LOAD

    // ---- epilogue: bias + relu -> fp16 -> g_h1 ----
    float2 bias[4];
#pragma unroll
    for (int nf = 0; nf < 4; ++nf) {
        int n = n0 + wn * 32 + nf * 8 + (lane & 3) * 2;
        bias[nf] = make_float2(b1[n], b1[n + 1]);
    }
#pragma unroll
    for (int mf = 0; mf < 4; ++mf) {
        int mA = m0 + wm * 64 + mf * 16 + (lane >> 2);
        __half* row0 = g_h1 + (size_t)mA * N_TOT;
        __half* row1 = row0 + (size_t)8 * N_TOT;
#pragma unroll
        for (int nf = 0; nf < 4; ++nf) {
            int n = n0 + wn * 32 + nf * 8 + (lane & 3) * 2;
            float v0 = fmaxf(acc[mf][nf][0] + bias[nf].x, 0.f);
            float v1 = fmaxf(acc[mf][nf][1] + bias[nf].y, 0.f);
            float v2 = fmaxf(acc[mf][nf][2] + bias[nf].x, 0.f);
            float v3 = fmaxf(acc[mf][nf][3] + bias[nf].y, 0.f);
            *reinterpret_cast<uint32_t*>(row0 + n) = packh(v0, v1);
            *reinterpret_cast<uint32_t*>(row1 + n) = packh(v2, v3);
        }
    }
}

// ---------------------------------------------------------------------------
// Kernel 4: GEMM2 + layer3 + gate-weighted sum -> predictions
//   CTA 256(M) x 128(N=H2), 512 thr = 16 warps (4x4), warp tile 64x32
//   32 chunks = 8 experts x 4 k-chunks; 4-stage ring, 1 sync/chunk
//   stage: A 32KB + B 16KB = 48KB -> 192KB + 8KB partials
// ---------------------------------------------------------------------------
#define G2_STAGE 49152
__global__ __launch_bounds__(512, 1)
void gemm2_kernel(const float* __restrict__ b2, const float* __restrict__ W3,
                  const float* __restrict__ b3, float* __restrict__ out) {
    extern __shared__ char smem[];
    const uint32_t sb = su32(smem);
    float* s_part = reinterpret_cast<float*>(smem + 4 * G2_STAGE); // [2][256][4]
    const int tid = threadIdx.x, lane = tid & 31, wid = tid >> 5;
    const int m0 = blockIdx.x * 256;
    const int wm = wid >> 2, wn = wid & 3;   // warp grid 4 x 4

    float predv = 0.f;

#define G2_LOAD(c_, s_) do {                                                   \
        const int e_ = (c_) >> 2, kb_ = ((c_) & 3) * KC;                       \
        const __half* Ab_ = g_h1  + (size_t)m0 * N_TOT + e_ * HID1 + kb_;      \
        const __half* Bb_ = g_w2t + (size_t)e_ * HID2 * HID1 + kb_;            \
        const uint32_t sA_ = sb + (s_) * G2_STAGE;                             \
        const uint32_t sB_ = sA_ + 32768;                                      \
        _Pragma("unroll")                                                      \
        for (int i_ = 0; i_ < 4; ++i_) {        /* A: 256 x 128B */            \
            int id_ = tid + i_ * 512;                                          \
            int r_ = id_ >> 3, c2_ = id_ & 7;                                  \
            cpasync16(sA_ + SW128(r_ * 128 + c2_ * 16),                        \
                      Ab_ + (size_t)r_ * N_TOT + c2_ * 8);                     \
        }                                                                      \
        _Pragma("unroll")                                                      \
        for (int i_ = 0; i_ < 2; ++i_) {        /* B: 128 x 128B */            \
            int id_ = tid + i_ * 512;                                          \
            int r_ = id_ >> 3, c2_ = id_ & 7;                                  \
            cpasync16(sB_ + SW128(r_ * 128 + c2_ * 16),                        \
                      Bb_ + (size_t)r_ * HID1 + c2_ * 8);                      \
        }                                                                      \
        CP_COMMIT();                                                           \
    } while (0)

    G2_LOAD(0, 0);
    G2_LOAD(1, 1);
    G2_LOAD(2, 2);

    const int lrow = lane & 15;
    const int lcol = (lane >> 4) * 16;

    float acc[4][4][4];

    for (int c = 0; c < 32; ++c) {
        const int e = c >> 2, kb = c & 3;
        if (kb == 0) {
#pragma unroll
            for (int i = 0; i < 4; ++i)
#pragma unroll
                for (int j = 0; j < 4; ++j)
#pragma unroll
                    for (int q = 0; q < 4; ++q) acc[i][j][q] = 0.f;
        }

        CP_WAIT(2);
        __syncthreads();
        if (c + 3 < 32) { G2_LOAD(c + 3, (c + 3) & 3); } else { CP_COMMIT(); }

        const uint32_t sA = sb + (c & 3) * G2_STAGE;
        const uint32_t sB = sA + 32768;
#pragma unroll
        for (int k16 = 0; k16 < 4; ++k16) {
            const int kbyte = k16 * 32 + lcol;
            uint32_t af[4][4];
#pragma unroll
            for (int mf = 0; mf < 4; ++mf)
                ldsm4(af[mf], sA + SW128((wm * 64 + mf * 16 + lrow) * 128 + kbyte));
            uint32_t bf[2][4];
#pragma unroll
            for (int nf2 = 0; nf2 < 2; ++nf2)
                ldsm4(bf[nf2], sB + SW128((wn * 32 + nf2 * 16 + lrow) * 128 + kbyte));
#pragma unroll
            for (int mf = 0; mf < 4; ++mf)
#pragma unroll
                for (int nf = 0; nf < 4; ++nf)
                    mma16816(acc[mf][nf], af[mf],
                             bf[nf >> 1][nf & 1], bf[nf >> 1][2 + (nf & 1)]);
        }

        if (kb == 3) {
            // relu(h2 + b2) . W3 per row -> partials (double-buffered)
            float* part = s_part + (e & 1) * 1024;
#pragma unroll
            for (int mf = 0; mf < 4; ++mf) {
#pragma unroll
                for (int h = 0; h < 2; ++h) {
                    float s = 0.f;
#pragma unroll
                    for (int nf = 0; nf < 4; ++nf) {
                        int n = wn * 32 + nf * 8 + (lane & 3) * 2;
                        float hv0 = fmaxf(acc[mf][nf][h * 2 + 0] + b2[e * HID2 + n], 0.f);
                        float hv1 = fmaxf(acc[mf][nf][h * 2 + 1] + b2[e * HID2 + n + 1], 0.f);
                        s += hv0 * W3[e * HID2 + n] + hv1 * W3[e * HID2 + n + 1];
                    }
                    s += __shfl_xor_sync(0xFFFFFFFFu, s, 1);
                    s += __shfl_xor_sync(0xFFFFFFFFu, s, 2);
                    if ((lane & 3) == 0) {
                        int m_local = wm * 64 + mf * 16 + h * 8 + (lane >> 2);
                        part[m_local * 4 + wn] = s;
                    }
                }
            }
            __syncthreads();
            if (tid < 256) {
                float dot = part[tid * 4 + 0] + part[tid * 4 + 1] +
                            part[tid * 4 + 2] + part[tid * 4 + 3];
                float g = out[(size_t)B_TOK + (size_t)(m0 + tid) * NEXP + e];
                predv += g * (dot + b3[e]);
            }
            // no trailing sync: next expert writes the other buffer, and
            // >=4 chunk-top syncs separate reuse of this one
        }
    }
#undef G2_LOAD
    if (tid < 256) out[m0 + tid] = predv;
}

// ---------------------------------------------------------------------------
// Launch
// ---------------------------------------------------------------------------
extern "C" void kernel_launch(void* const* d_in, const int* in_sizes, int n_in,
                              void* d_out, int out_size) {
    const float* x  = (const float*)d_in[0];
    const float* W1 = (const float*)d_in[1];
    const float* b1 = (const float*)d_in[2];
    const float* W2 = (const float*)d_in[3];
    const float* b2 = (const float*)d_in[4];
    const float* W3 = (const float*)d_in[5];
    const float* b3 = (const float*)d_in[6];
    const float* Wg = (const float*)d_in[7];
    const float* bg = (const float*)d_in[8];
    float* out = (float*)d_out;

    const int SMEM1 = 4 * G1_STAGE;           // 196608
    const int SMEM2 = 4 * G2_STAGE + 8192;    // 204800
    cudaFuncSetAttribute(gemm1_kernel, cudaFuncAttributeMaxDynamicSharedMemorySize, SMEM1);
    cudaFuncSetAttribute(gemm2_kernel, cudaFuncAttributeMaxDynamicSharedMemorySize, SMEM2);

    pack_weights_kernel<<<512, 256>>>(W1, W2);
    gate_convert_kernel<<<B_TOK / 8, 256>>>(x, Wg, bg, out);
    gemm1_kernel<<<dim3(N_TOT / 256, B_TOK / 128), 512, SMEM1>>>(b1);
    gemm2_kernel<<<B_TOK / 256, 512, SMEM2>>>(b2, W3, b3, out);
}

// round 8
// speedup vs baseline: 1.1025x; 1.0840x over previous
#include <cuda_runtime.h>
#include <cuda_fp16.h>
#include <cstdint>

// ---------------------------------------------------------------------------
// Problem constants
// ---------------------------------------------------------------------------
#define B_TOK  65536
#define IN_D   1280
#define NEXP   8
#define HID1   256
#define HID2   128
#define N_TOT  2048              // NEXP * HID1
#define KC     64                // K chunk (64 halfs = 128B rows)

// ---------------------------------------------------------------------------
// Scratch (device globals: allocation-free rule)
// ---------------------------------------------------------------------------
__device__ __half g_xh [(size_t)B_TOK * IN_D];       // x in fp16        (160 MB)
__device__ __half g_w1t[(size_t)N_TOT * IN_D];       // W1 packed [n][k] (5.2 MB)
__device__ __half g_h1 [(size_t)B_TOK * N_TOT];      // h1 fp16          (256 MB)
__device__ __half g_w2t[(size_t)NEXP * HID2 * HID1]; // W2 packed [e][n][k]

// ---------------------------------------------------------------------------
// PTX helpers (base sm_103: mma.sync + ldmatrix + cp.async)
// ---------------------------------------------------------------------------
__device__ __forceinline__ uint32_t su32(const void* p) {
    uint32_t a;
    asm("{ .reg .u64 t; cvta.to.shared.u64 t, %1; cvt.u32.u64 %0, t; }"
        : "=r"(a) : "l"(p));
    return a;
}

__device__ __forceinline__ void cpasync16(uint32_t dst, const void* src) {
    asm volatile("cp.async.cg.shared.global [%0], [%1], 16;"
                 :: "r"(dst), "l"(src) : "memory");
}
#define CP_COMMIT() asm volatile("cp.async.commit_group;" ::: "memory")
#define CP_WAIT(n)  asm volatile("cp.async.wait_group %0;" :: "n"(n) : "memory")

__device__ __forceinline__ void ldsm4(uint32_t (&r)[4], uint32_t addr) {
    asm volatile("ldmatrix.sync.aligned.m8n8.x4.shared.b16 {%0,%1,%2,%3}, [%4];"
                 : "=r"(r[0]), "=r"(r[1]), "=r"(r[2]), "=r"(r[3]) : "r"(addr));
}

__device__ __forceinline__ void mma16816(float* d, const uint32_t* a,
                                         uint32_t b0, uint32_t b1) {
    asm volatile(
        "mma.sync.aligned.m16n8k16.row.col.f32.f16.f16.f32 "
        "{%0,%1,%2,%3},{%4,%5,%6,%7},{%8,%9},{%0,%1,%2,%3};"
        : "+f"(d[0]), "+f"(d[1]), "+f"(d[2]), "+f"(d[3])
        : "r"(a[0]), "r"(a[1]), "r"(a[2]), "r"(a[3]), "r"(b0), "r"(b1));
}

// SW128(row*128+col) == row*128 + (col ^ ((row&7)<<4))  for col<128
#define SWROW(r, c) ((uint32_t)((r) * 128 + ((c) ^ (((r) & 7) << 4))))

__device__ __forceinline__ uint32_t packh(float a, float b) {
    __half2 h = __floats2half2_rn(a, b);
    return *reinterpret_cast<uint32_t*>(&h);
}

// ---------------------------------------------------------------------------
// Kernel 1: pack weights into fp16 K-major B-operand layouts
// ---------------------------------------------------------------------------
__global__ void pack_weights_kernel(const float* __restrict__ W1,
                                    const float* __restrict__ W2) {
    const int stride = gridDim.x * blockDim.x;
    int idx = blockIdx.x * blockDim.x + threadIdx.x;
    for (int i = idx; i < N_TOT * IN_D; i += stride) {
        int n = i / IN_D, k = i % IN_D;
        g_w1t[i] = __float2half_rn(W1[((size_t)(n >> 8) * IN_D + k) * HID1 + (n & 255)]);
    }
    for (int i = idx; i < NEXP * HID2 * HID1; i += stride) {
        int e = i >> 15;
        int r = i & 32767;
        int n = r >> 8;           // h2  (0..127)
        int k = r & 255;          // h1  (0..255)
        g_w2t[i] = __float2half_rn(W2[(size_t)e * HID1 * HID2 + (size_t)k * HID2 + n]);
    }
}

// ---------------------------------------------------------------------------
// Kernel 2: gate (fp32, one warp per token) + x -> fp16 conversion
// ---------------------------------------------------------------------------
__global__ __launch_bounds__(256) void gate_convert_kernel(
    const float* __restrict__ x, const float* __restrict__ Wg,
    const float* __restrict__ bg, float* __restrict__ out) {
    const int warp = (blockIdx.x * blockDim.x + threadIdx.x) >> 5;  // token id
    const int lane = threadIdx.x & 31;
    const float* xr = x + (size_t)warp * IN_D;
    __half* xo = g_xh + (size_t)warp * IN_D;

    float acc[NEXP];
#pragma unroll
    for (int e = 0; e < NEXP; ++e) acc[e] = 0.f;

    for (int k = lane; k < IN_D; k += 32) {
        float xv = xr[k];
        xo[k] = __float2half_rn(xv);
        float4 wa = *reinterpret_cast<const float4*>(Wg + (size_t)k * NEXP);
        float4 wb = *reinterpret_cast<const float4*>(Wg + (size_t)k * NEXP + 4);
        acc[0] += xv * wa.x; acc[1] += xv * wa.y;
        acc[2] += xv * wa.z; acc[3] += xv * wa.w;
        acc[4] += xv * wb.x; acc[5] += xv * wb.y;
        acc[6] += xv * wb.z; acc[7] += xv * wb.w;
    }
#pragma unroll
    for (int e = 0; e < NEXP; ++e) {
        float v = acc[e];
        v += __shfl_xor_sync(0xFFFFFFFFu, v, 16);
        v += __shfl_xor_sync(0xFFFFFFFFu, v, 8);
        v += __shfl_xor_sync(0xFFFFFFFFu, v, 4);
        v += __shfl_xor_sync(0xFFFFFFFFu, v, 2);
        v += __shfl_xor_sync(0xFFFFFFFFu, v, 1);
        acc[e] = v + bg[e];
    }
    float m = acc[0];
#pragma unroll
    for (int e = 1; e < NEXP; ++e) m = fmaxf(m, acc[e]);
    float s = 0.f;
#pragma unroll
    for (int e = 0; e < NEXP; ++e) { acc[e] = expf(acc[e] - m); s += acc[e]; }
    float inv = 1.f / s;
    if (lane < NEXP)
        out[(size_t)B_TOK + (size_t)warp * NEXP + lane] = acc[lane] * inv;
}

// ---------------------------------------------------------------------------
// GEMM config shared by both kernels:
//   CTA tile 128x128, 256 thr = 8 warps (2x4), warp tile 64x32
//   3-stage cp.async ring (A 16KB + B 16KB per stage = 32KB), 96KB/CTA
//   -> 2 CTAs per SM for barrier/latency overlap
// ---------------------------------------------------------------------------
#define G_STAGE 32768

// ---------------------------------------------------------------------------
// Kernel 3: GEMM1 h1 = relu(x @ W1cat + b1)
// ---------------------------------------------------------------------------
__global__ __launch_bounds__(256, 2)
void gemm1_kernel(const float* __restrict__ b1) {
    extern __shared__ char smem[];
    const uint32_t sb = su32(smem);
    const int tid = threadIdx.x, lane = tid & 31, wid = tid >> 5;
    const int m0 = blockIdx.y * 128;
    const int n0 = blockIdx.x * 128;
    const int wm = wid >> 2, wn = wid & 3;   // warp grid 2 x 4

    // ---- hoisted loader state (per-thread, loop-invariant) ----
    const int r0 = tid >> 3, c0 = tid & 7;           // i-th chunk: row r0+32*i
    const uint32_t so0 = SWROW(r0, c0 * 16);         // + i*4096 (row&7 invariant)
    const __half* gA0 = g_xh  + (size_t)(m0 + r0) * IN_D + c0 * 8;
    const __half* gB0 = g_w1t + (size_t)(n0 + r0) * IN_D + c0 * 8;

#define G1_LOAD(it_, s_) do {                                                  \
        const int k0_ = (it_) * KC;                                            \
        const uint32_t sA_ = sb + (s_) * G_STAGE;                              \
        const uint32_t sB_ = sA_ + 16384;                                      \
        _Pragma("unroll")                                                      \
        for (int i_ = 0; i_ < 4; ++i_)                                         \
            cpasync16(sA_ + so0 + i_ * 4096,                                   \
                      gA0 + (size_t)i_ * 32 * IN_D + k0_);                     \
        _Pragma("unroll")                                                      \
        for (int i_ = 0; i_ < 4; ++i_)                                         \
            cpasync16(sB_ + so0 + i_ * 4096,                                   \
                      gB0 + (size_t)i_ * 32 * IN_D + k0_);                     \
        CP_COMMIT();                                                           \
    } while (0)

    float acc[4][4][4];
#pragma unroll
    for (int i = 0; i < 4; ++i)
#pragma unroll
        for (int j = 0; j < 4; ++j)
#pragma unroll
            for (int q = 0; q < 4; ++q) acc[i][j][q] = 0.f;

    // ---- hoisted ldsm bases (XOR with k16<<5 gives per-k16 address) ----
    const int lrow = lane & 15;
    const int lcol = (lane >> 4) * 16;
    uint32_t baseA[4], baseB[2];
#pragma unroll
    for (int mf = 0; mf < 4; ++mf) {
        int r = wm * 64 + mf * 16 + lrow;
        baseA[mf] = SWROW(r, lcol);
    }
#pragma unroll
    for (int nf2 = 0; nf2 < 2; ++nf2) {
        int r = wn * 32 + nf2 * 16 + lrow;
        baseB[nf2] = 16384u + SWROW(r, lcol);
    }

    const int NIT = IN_D / KC;   // 20
    G1_LOAD(0, 0);
    G1_LOAD(1, 1);

    int stage = 0;
    for (int it = 0; it < NIT; ++it) {
        CP_WAIT(1);            // stage (it) resident
        __syncthreads();       // stage (it-1) consumers done -> (it+2) may overwrite
        if (it + 2 < NIT) {
            int s2 = stage + 2; if (s2 >= 3) s2 -= 3;
            G1_LOAD(it + 2, s2);
        } else { CP_COMMIT(); }

        const uint32_t sS = sb + stage * G_STAGE;
#pragma unroll
        for (int k16 = 0; k16 < 4; ++k16) {
            const uint32_t kx = (uint32_t)(k16 << 5);
            uint32_t af[4][4];
#pragma unroll
            for (int mf = 0; mf < 4; ++mf)
                ldsm4(af[mf], sS + (baseA[mf] ^ kx));
            uint32_t bf[2][4];
#pragma unroll
            for (int nf2 = 0; nf2 < 2; ++nf2)
                ldsm4(bf[nf2], sS + (baseB[nf2] ^ kx));
#pragma unroll
            for (int mf = 0; mf < 4; ++mf)
#pragma unroll
                for (int nf = 0; nf < 4; ++nf)
                    mma16816(acc[mf][nf], af[mf],
                             bf[nf >> 1][nf & 1], bf[nf >> 1][2 + (nf & 1)]);
        }
        if (++stage == 3) stage = 0;
    }
#undef G1_LOAD

    // ---- epilogue: bias + relu -> fp16 -> g_h1 ----
    float2 bias[4];
#pragma unroll
    for (int nf = 0; nf < 4; ++nf) {
        int n = n0 + wn * 32 + nf * 8 + (lane & 3) * 2;
        bias[nf] = make_float2(b1[n], b1[n + 1]);
    }
#pragma unroll
    for (int mf = 0; mf < 4; ++mf) {
        int mA = m0 + wm * 64 + mf * 16 + (lane >> 2);
        __half* row0 = g_h1 + (size_t)mA * N_TOT;
        __half* row1 = row0 + (size_t)8 * N_TOT;
#pragma unroll
        for (int nf = 0; nf < 4; ++nf) {
            int n = n0 + wn * 32 + nf * 8 + (lane & 3) * 2;
            float v0 = fmaxf(acc[mf][nf][0] + bias[nf].x, 0.f);
            float v1 = fmaxf(acc[mf][nf][1] + bias[nf].y, 0.f);
            float v2 = fmaxf(acc[mf][nf][2] + bias[nf].x, 0.f);
            float v3 = fmaxf(acc[mf][nf][3] + bias[nf].y, 0.f);
            *reinterpret_cast<uint32_t*>(row0 + n) = packh(v0, v1);
            *reinterpret_cast<uint32_t*>(row1 + n) = packh(v2, v3);
        }
    }
}

// ---------------------------------------------------------------------------
// Kernel 4: GEMM2 + layer3 + gate-weighted sum -> predictions
//   CTA 128(M) x 128(N=H2); 32 chunks = 8 experts x 4 k-chunks
// ---------------------------------------------------------------------------
__global__ __launch_bounds__(256, 2)
void gemm2_kernel(const float* __restrict__ b2, const float* __restrict__ W3,
                  const float* __restrict__ b3, float* __restrict__ out) {
    extern __shared__ char smem[];
    const uint32_t sb = su32(smem);
    float* s_part = reinterpret_cast<float*>(smem + 3 * G_STAGE); // [2][128][4]
    const int tid = threadIdx.x, lane = tid & 31, wid = tid >> 5;
    const int m0 = blockIdx.x * 128;
    const int wm = wid >> 2, wn = wid & 3;   // warp grid 2 x 4

    float predv = 0.f;

    // hoisted loader state: A rows = tokens, chunk offset advances by 64 halfs
    const int r0 = tid >> 3, c0 = tid & 7;
    const uint32_t so0 = SWROW(r0, c0 * 16);
    const __half* gA0 = g_h1  + (size_t)(m0 + r0) * N_TOT + c0 * 8;
    const __half* gB0 = g_w2t + (size_t)r0 * HID1 + c0 * 8;

#define G2_LOAD(c_, s_) do {                                                   \
        const uint32_t sA_ = sb + (s_) * G_STAGE;                              \
        const uint32_t sB_ = sA_ + 16384;                                      \
        const int aoff_ = (c_) * KC;               /* (4e+kb)*64 == c*64 */    \
        const int boff_ = ((c_) >> 2) * (HID2 * HID1) + ((c_) & 3) * KC;       \
        _Pragma("unroll")                                                      \
        for (int i_ = 0; i_ < 4; ++i_)                                         \
            cpasync16(sA_ + so0 + i_ * 4096,                                   \
                      gA0 + (size_t)i_ * 32 * N_TOT + aoff_);                  \
        _Pragma("unroll")                                                      \
        for (int i_ = 0; i_ < 4; ++i_)                                         \
            cpasync16(sB_ + so0 + i_ * 4096,                                   \
                      gB0 + (size_t)i_ * 32 * HID1 + boff_);                   \
        CP_COMMIT();                                                           \
    } while (0)

    const int lrow = lane & 15;
    const int lcol = (lane >> 4) * 16;
    uint32_t baseA[4], baseB[2];
#pragma unroll
    for (int mf = 0; mf < 4; ++mf) {
        int r = wm * 64 + mf * 16 + lrow;
        baseA[mf] = SWROW(r, lcol);
    }
#pragma unroll
    for (int nf2 = 0; nf2 < 2; ++nf2) {
        int r = wn * 32 + nf2 * 16 + lrow;
        baseB[nf2] = 16384u + SWROW(r, lcol);
    }

    G2_LOAD(0, 0);
    G2_LOAD(1, 1);

    float acc[4][4][4];
    int stage = 0;

    for (int c = 0; c < 32; ++c) {
        const int e = c >> 2, kb = c & 3;
        if (kb == 0) {
#pragma unroll
            for (int i = 0; i < 4; ++i)
#pragma unroll
                for (int j = 0; j < 4; ++j)
#pragma unroll
                    for (int q = 0; q < 4; ++q) acc[i][j][q] = 0.f;
        }

        CP_WAIT(1);
        __syncthreads();
        if (c + 2 < 32) {
            int s2 = stage + 2; if (s2 >= 3) s2 -= 3;
            G2_LOAD(c + 2, s2);
        } else { CP_COMMIT(); }

        const uint32_t sS = sb + stage * G_STAGE;
#pragma unroll
        for (int k16 = 0; k16 < 4; ++k16) {
            const uint32_t kx = (uint32_t)(k16 << 5);
            uint32_t af[4][4];
#pragma unroll
            for (int mf = 0; mf < 4; ++mf)
                ldsm4(af[mf], sS + (baseA[mf] ^ kx));
            uint32_t bf[2][4];
#pragma unroll
            for (int nf2 = 0; nf2 < 2; ++nf2)
                ldsm4(bf[nf2], sS + (baseB[nf2] ^ kx));
#pragma unroll
            for (int mf = 0; mf < 4; ++mf)
#pragma unroll
                for (int nf = 0; nf < 4; ++nf)
                    mma16816(acc[mf][nf], af[mf],
                             bf[nf >> 1][nf & 1], bf[nf >> 1][2 + (nf & 1)]);
        }
        if (++stage == 3) stage = 0;

        if (kb == 3) {
            // relu(h2 + b2) . W3 per row -> partials (double-buffered)
            float2 b2v[4], w3v[4];
#pragma unroll
            for (int nf = 0; nf < 4; ++nf) {
                int n = e * HID2 + wn * 32 + nf * 8 + (lane & 3) * 2;
                b2v[nf] = make_float2(b2[n], b2[n + 1]);
                w3v[nf] = make_float2(W3[n], W3[n + 1]);
            }
            float* part = s_part + (e & 1) * 512;
#pragma unroll
            for (int mf = 0; mf < 4; ++mf) {
#pragma unroll
                for (int h = 0; h < 2; ++h) {
                    float s = 0.f;
#pragma unroll
                    for (int nf = 0; nf < 4; ++nf) {
                        float hv0 = fmaxf(acc[mf][nf][h * 2 + 0] + b2v[nf].x, 0.f);
                        float hv1 = fmaxf(acc[mf][nf][h * 2 + 1] + b2v[nf].y, 0.f);
                        s += hv0 * w3v[nf].x + hv1 * w3v[nf].y;
                    }
                    s += __shfl_xor_sync(0xFFFFFFFFu, s, 1);
                    s += __shfl_xor_sync(0xFFFFFFFFu, s, 2);
                    if ((lane & 3) == 0) {
                        int m_local = wm * 64 + mf * 16 + h * 8 + (lane >> 2);
                        part[m_local * 4 + wn] = s;
                    }
                }
            }
            __syncthreads();
            if (tid < 128) {
                float dot = part[tid * 4 + 0] + part[tid * 4 + 1] +
                            part[tid * 4 + 2] + part[tid * 4 + 3];
                float g = out[(size_t)B_TOK + (size_t)(m0 + tid) * NEXP + e];
                predv += g * (dot + b3[e]);
            }
            // no trailing sync: next expert uses the other part buffer, and
            // >=4 chunk-top syncs separate reuse of this one
        }
    }
#undef G2_LOAD
    if (tid < 128) out[m0 + tid] = predv;
}

// ---------------------------------------------------------------------------
// Launch
// ---------------------------------------------------------------------------
extern "C" void kernel_launch(void* const* d_in, const int* in_sizes, int n_in,
                              void* d_out, int out_size) {
    const float* x  = (const float*)d_in[0];
    const float* W1 = (const float*)d_in[1];
    const float* b1 = (const float*)d_in[2];
    const float* W2 = (const float*)d_in[3];
    const float* b2 = (const float*)d_in[4];
    const float* W3 = (const float*)d_in[5];
    const float* b3 = (const float*)d_in[6];
    const float* Wg = (const float*)d_in[7];
    const float* bg = (const float*)d_in[8];
    float* out = (float*)d_out;

    const int SMEM1 = 3 * G_STAGE;            // 98304
    const int SMEM2 = 3 * G_STAGE + 4096;     // 102400
    cudaFuncSetAttribute(gemm1_kernel, cudaFuncAttributeMaxDynamicSharedMemorySize, SMEM1);
    cudaFuncSetAttribute(gemm2_kernel, cudaFuncAttributeMaxDynamicSharedMemorySize, SMEM2);

    pack_weights_kernel<<<512, 256>>>(W1, W2);
    gate_convert_kernel<<<B_TOK / 8, 256>>>(x, Wg, bg, out);
    gemm1_kernel<<<dim3(N_TOT / 128, B_TOK / 128), 256, SMEM1>>>(b1);
    gemm2_kernel<<<B_TOK / 128, 256, SMEM2>>>(b2, W3, b3, out);
}